// round 4
// baseline (speedup 1.0000x reference)
#include <cuda_runtime.h>
#include <math.h>

#define S_LEN 2048
#define EMB   2048
#define NB    2
#define NH    16
#define HD    128
#define BHN   (NB*NH)          // 32
#define M_TOT (NB*S_LEN)       // 4096

// -------- scratch (no allocations allowed; __device__ globals) --------
__device__ float g_q  [(size_t)BHN * S_LEN * HD];   // rope'd Q, (B,H,S,D)
__device__ float g_kr [(size_t)BHN * S_LEN * HD];   // rope'd K, (B,H,S,D)
__device__ float g_ctx[(size_t)NB  * S_LEN * EMB];  // attention context, (B,S,E)

// ============================================================================
// SGEMM (NT): C[m][n] = sum_k A[m][k] * B[n][k]
// A: M x K row-major, B: N x K row-major. M=4096, N=2048, K=2048 (hardcoded divisible).
// MODE 0: C row-major (M x EMB). MODE 1: head layout (B,H,S,D).
// ============================================================================
#define GBK 16
#define GST 132

template<int MODE>
__global__ void __launch_bounds__(256, 2)
sgemm_nt(const float* __restrict__ A, const float* __restrict__ Bm,
         float* __restrict__ C, int K)
{
    __shared__ float As[GBK][GST];
    __shared__ float Bs[GBK][GST];

    const int t  = threadIdx.x;
    const int bn = blockIdx.x, bm = blockIdx.y;
    const int ty = t >> 4, tx = t & 15;
    const int lr = t >> 2;            // 0..63
    const int lc = (t & 3) * 4;       // 0,4,8,12

    const float* Ap = A  + (size_t)(bm * 128 + lr) * K + lc;
    const float* Bp = Bm + (size_t)(bn * 128 + lr) * K + lc;

    float4 pa0 = *(const float4*)(Ap);
    float4 pa1 = *(const float4*)(Ap + (size_t)64 * K);
    float4 pb0 = *(const float4*)(Bp);
    float4 pb1 = *(const float4*)(Bp + (size_t)64 * K);

    float acc[8][8];
    #pragma unroll
    for (int i = 0; i < 8; i++)
        #pragma unroll
        for (int j = 0; j < 8; j++) acc[i][j] = 0.f;

    const int ktiles = K / GBK;
    for (int kt = 0; kt < ktiles; kt++) {
        // store prefetched tile (transposed) to smem
        As[lc+0][lr]    = pa0.x; As[lc+1][lr]    = pa0.y; As[lc+2][lr]    = pa0.z; As[lc+3][lr]    = pa0.w;
        As[lc+0][lr+64] = pa1.x; As[lc+1][lr+64] = pa1.y; As[lc+2][lr+64] = pa1.z; As[lc+3][lr+64] = pa1.w;
        Bs[lc+0][lr]    = pb0.x; Bs[lc+1][lr]    = pb0.y; Bs[lc+2][lr]    = pb0.z; Bs[lc+3][lr]    = pb0.w;
        Bs[lc+0][lr+64] = pb1.x; Bs[lc+1][lr+64] = pb1.y; Bs[lc+2][lr+64] = pb1.z; Bs[lc+3][lr+64] = pb1.w;
        __syncthreads();

        if (kt + 1 < ktiles) {
            Ap += GBK; Bp += GBK;
            pa0 = *(const float4*)(Ap);
            pa1 = *(const float4*)(Ap + (size_t)64 * K);
            pb0 = *(const float4*)(Bp);
            pb1 = *(const float4*)(Bp + (size_t)64 * K);
        }

        #pragma unroll
        for (int kk = 0; kk < GBK; kk++) {
            float4 a0 = *(const float4*)&As[kk][ty*4];
            float4 a1 = *(const float4*)&As[kk][64 + ty*4];
            float4 b0 = *(const float4*)&Bs[kk][tx*4];
            float4 b1 = *(const float4*)&Bs[kk][64 + tx*4];
            float av[8] = {a0.x,a0.y,a0.z,a0.w, a1.x,a1.y,a1.z,a1.w};
            float bv[8] = {b0.x,b0.y,b0.z,b0.w, b1.x,b1.y,b1.z,b1.w};
            #pragma unroll
            for (int i = 0; i < 8; i++)
                #pragma unroll
                for (int j = 0; j < 8; j++)
                    acc[i][j] += av[i] * bv[j];
        }
        __syncthreads();
    }

    // epilogue
    #pragma unroll
    for (int i = 0; i < 8; i++) {
        int rloc = (i < 4) ? (ty*4 + i) : (64 + ty*4 + (i - 4));
        int row  = bm * 128 + rloc;
        #pragma unroll
        for (int jh = 0; jh < 2; jh++) {
            int col = bn * 128 + jh*64 + tx*4;
            float4 vo = make_float4(acc[i][jh*4+0], acc[i][jh*4+1],
                                    acc[i][jh*4+2], acc[i][jh*4+3]);
            if (MODE == 0) {
                *(float4*)(C + (size_t)row * EMB + col) = vo;
            } else {
                int b = row >> 11, s = row & (S_LEN - 1);
                int h = col >> 7,  d = col & (HD - 1);
                *(float4*)(C + (((size_t)(b * NH + h) * S_LEN + s) << 7) + d) = vo;
            }
        }
    }
}

// ============================================================================
// RoPE: interleaved pairs within each head dim. q in-place, k -> kout.
// ============================================================================
__global__ void rope_kernel(float* __restrict__ q, const float* __restrict__ kin,
                            float* __restrict__ kout)
{
    int tid = blockIdx.x * blockDim.x + threadIdx.x;
    int dd = tid & 63;
    int s  = (tid >> 6) & (S_LEN - 1);
    int bh = tid >> 17;
    if (bh >= BHN) return;

    float freq = powf(10000.0f, -(float)(2 * dd) / 128.0f);
    float ang  = (float)s * freq;
    float sn, cs;
    sincosf(ang, &sn, &cs);

    size_t base = (((size_t)bh * S_LEN) + s) * HD + dd * 2;
    float x1 = q[base], x2 = q[base + 1];
    q[base]     = x1 * cs - x2 * sn;
    q[base + 1] = x1 * sn + x2 * cs;

    float y1 = kin[base], y2 = kin[base + 1];
    kout[base]     = y1 * cs - y2 * sn;
    kout[base + 1] = y1 * sn + y2 * cs;
}

// ============================================================================
// Flash attention (causal, online softmax). BM=BN=64, D=128.
// grid: (S/64, B*H), 256 threads.
// ============================================================================
#define QSTR 68
#define VSTR 132
#define ATT_SMEM ((128*QSTR*2 + 64*VSTR + 64*QSTR) * 4)   // 120832 bytes

__global__ void __launch_bounds__(256, 1)
attn_kernel(const float* __restrict__ Q, const float* __restrict__ Kr,
            const float* __restrict__ V, float* __restrict__ ctx)
{
    extern __shared__ float sm[];
    float* q_t = sm;                     // [128][QSTR]  q_t[d*QSTR + r]
    float* k_t = q_t + 128 * QSTR;       // [128][QSTR]
    float* v_s = k_t + 128 * QSTR;       // [64][VSTR]   row-major
    float* s_s = v_s + 64 * VSTR;        // [64][QSTR]

    const int t  = threadIdx.x;
    const int qt = blockIdx.x;
    const int bh = blockIdx.y;

    const float* qbase = Q  + ((size_t)bh * S_LEN + qt * 64) * HD;
    const float* kbase = Kr + (size_t)bh * S_LEN * HD;
    const float* vbase = V  + (size_t)bh * S_LEN * HD;

    const int ty = t >> 4, tx = t & 15;   // S-compute mapping (16x16, 4x4 microtile)
    const int r  = t >> 2, c4 = t & 3;    // softmax/O mapping (4 threads per row)

    // load Q tile transposed into smem
    #pragma unroll
    for (int it = 0; it < 8; it++) {
        int idx = t + it * 256;
        int rr = idx >> 5;
        int cc = (idx & 31) * 4;
        float4 v4 = *(const float4*)(qbase + (size_t)rr * HD + cc);
        q_t[(cc+0)*QSTR + rr] = v4.x;
        q_t[(cc+1)*QSTR + rr] = v4.y;
        q_t[(cc+2)*QSTR + rr] = v4.z;
        q_t[(cc+3)*QSTR + rr] = v4.w;
    }

    float m_prev = -1e30f, lsum = 0.f;
    float4 acc[8];
    #pragma unroll
    for (int jj = 0; jj < 8; jj++) acc[jj] = make_float4(0.f, 0.f, 0.f, 0.f);

    const float scale = 0.088388347648318447f;  // 1/sqrt(128)

    for (int j = 0; j <= qt; j++) {
        __syncthreads();   // protect smem reuse from previous iteration

        // load K (transposed) and V tiles
        #pragma unroll
        for (int it = 0; it < 8; it++) {
            int idx = t + it * 256;
            int rr = idx >> 5;
            int cc = (idx & 31) * 4;
            float4 kv = *(const float4*)(kbase + (size_t)(j*64 + rr) * HD + cc);
            k_t[(cc+0)*QSTR + rr] = kv.x;
            k_t[(cc+1)*QSTR + rr] = kv.y;
            k_t[(cc+2)*QSTR + rr] = kv.z;
            k_t[(cc+3)*QSTR + rr] = kv.w;
            float4 vv = *(const float4*)(vbase + (size_t)(j*64 + rr) * HD + cc);
            *(float4*)&v_s[rr * VSTR + cc] = vv;
        }
        __syncthreads();

        // S = Q K^T (each thread 4x4)
        float racc[4][4];
        #pragma unroll
        for (int i = 0; i < 4; i++)
            #pragma unroll
            for (int jx = 0; jx < 4; jx++) racc[i][jx] = 0.f;

        #pragma unroll 8
        for (int d = 0; d < HD; d++) {
            float4 aq = *(const float4*)&q_t[d*QSTR + ty*4];
            float4 bk = *(const float4*)&k_t[d*QSTR + tx*4];
            float av[4] = {aq.x, aq.y, aq.z, aq.w};
            float bv[4] = {bk.x, bk.y, bk.z, bk.w};
            #pragma unroll
            for (int i = 0; i < 4; i++)
                #pragma unroll
                for (int jx = 0; jx < 4; jx++)
                    racc[i][jx] += av[i] * bv[jx];
        }
        #pragma unroll
        for (int i = 0; i < 4; i++) {
            float4 sv = make_float4(racc[i][0]*scale, racc[i][1]*scale,
                                    racc[i][2]*scale, racc[i][3]*scale);
            *(float4*)&s_s[(ty*4 + i)*QSTR + tx*4] = sv;
        }
        __syncthreads();

        // online softmax: thread handles row r, cols c4*16..c4*16+15
        float stmp[16];
        float mloc = -1e30f;
        const bool diag = (j == qt);
        #pragma unroll
        for (int u = 0; u < 16; u++) {
            int col = c4*16 + u;
            float sv = s_s[r*QSTR + col];
            if (diag && col > r) sv = -1e30f;
            stmp[u] = sv;
            mloc = fmaxf(mloc, sv);
        }
        mloc = fmaxf(mloc, __shfl_xor_sync(0xffffffffu, mloc, 1));
        mloc = fmaxf(mloc, __shfl_xor_sync(0xffffffffu, mloc, 2));
        float mnew  = fmaxf(m_prev, mloc);
        float alpha = __expf(m_prev - mnew);
        float lloc = 0.f;
        #pragma unroll
        for (int u = 0; u < 16; u++) {
            float p = __expf(stmp[u] - mnew);
            lloc += p;
            s_s[r*QSTR + c4*16 + u] = p;
        }
        lloc += __shfl_xor_sync(0xffffffffu, lloc, 1);
        lloc += __shfl_xor_sync(0xffffffffu, lloc, 2);
        lsum = lsum * alpha + lloc;
        m_prev = mnew;
        #pragma unroll
        for (int jj = 0; jj < 8; jj++) {
            acc[jj].x *= alpha; acc[jj].y *= alpha;
            acc[jj].z *= alpha; acc[jj].w *= alpha;
        }
        __syncthreads();   // P visible to all row threads

        // O += P * V  (thread owns d = (c4 + 4*jj)*4 .. +3)
        #pragma unroll 4
        for (int kc = 0; kc < 64; kc++) {
            float p = s_s[r*QSTR + kc];
            #pragma unroll
            for (int jj = 0; jj < 8; jj++) {
                float4 vv = *(const float4*)&v_s[kc*VSTR + (c4 + 4*jj)*4];
                acc[jj].x += p * vv.x; acc[jj].y += p * vv.y;
                acc[jj].z += p * vv.z; acc[jj].w += p * vv.w;
            }
        }
    }

    // normalize + write ctx (B,S,E)
    float inv = 1.f / lsum;
    int b = bh >> 4, h = bh & 15;
    float* outp = g_ctx;  // silence unused warning path (ctx param used below)
    outp = ctx + ((size_t)b * S_LEN + qt*64 + r) * EMB + h * HD;
    #pragma unroll
    for (int jj = 0; jj < 8; jj++) {
        int d = (c4 + 4*jj) * 4;
        float4 o = make_float4(acc[jj].x*inv, acc[jj].y*inv,
                               acc[jj].z*inv, acc[jj].w*inv);
        *(float4*)(outp + d) = o;
    }
}

// ============================================================================
// launch
// ============================================================================
extern "C" void kernel_launch(void* const* d_in, const int* in_sizes, int n_in,
                              void* d_out, int out_size)
{
    (void)in_sizes; (void)n_in; (void)out_size;
    const float* x  = (const float*)d_in[0];
    const float* Wq = (const float*)d_in[1];
    const float* Wk = (const float*)d_in[2];
    const float* Wv = (const float*)d_in[3];
    const float* Wo = (const float*)d_in[4];

    float* out  = (float*)d_out;
    float* outK = out  + (size_t)NB * S_LEN * EMB;     // k output (B,H,S,D)
    float* outV = outK + (size_t)BHN * S_LEN * HD;     // v output (B,H,S,D)

    float *qp, *krp, *ctxp;
    cudaGetSymbolAddress((void**)&qp,   g_q);
    cudaGetSymbolAddress((void**)&krp,  g_kr);
    cudaGetSymbolAddress((void**)&ctxp, g_ctx);

    cudaFuncSetAttribute(attn_kernel,
                         cudaFuncAttributeMaxDynamicSharedMemorySize, ATT_SMEM);

    dim3 ggrid(EMB / 128, M_TOT / 128);
    sgemm_nt<1><<<ggrid, 256>>>(x, Wq, qp,   EMB);   // Q -> scratch (B,H,S,D)
    sgemm_nt<1><<<ggrid, 256>>>(x, Wk, outK, EMB);   // K -> d_out (pre-rope output)
    sgemm_nt<1><<<ggrid, 256>>>(x, Wv, outV, EMB);   // V -> d_out

    rope_kernel<<<(BHN * S_LEN * 64) / 256, 256>>>(qp, outK, krp);

    attn_kernel<<<dim3(S_LEN / 64, BHN), 256, ATT_SMEM>>>(qp, krp, outV, ctxp);

    sgemm_nt<0><<<ggrid, 256>>>(ctxp, Wo, out, EMB); // attn_out
}

// round 6
// speedup vs baseline: 1.4360x; 1.4360x over previous
#include <cuda_runtime.h>
#include <cuda_bf16.h>
#include <math.h>
#include <stdint.h>

#define S_LEN 2048
#define EMB   2048
#define NB    2
#define NH    16
#define HD    128
#define BHN   (NB*NH)          // 32
#define M_TOT (NB*S_LEN)       // 4096

// -------- scratch (__device__ globals; no allocations allowed) --------
__device__ float g_q  [(size_t)BHN * S_LEN * HD];   // rope'd Q, (B,H,S,D)
__device__ float g_kr [(size_t)BHN * S_LEN * HD];   // rope'd K, (B,H,S,D)
__device__ float g_ctx[(size_t)NB  * S_LEN * EMB];  // attention context, (B,S,E)
__device__ __nv_bfloat16 g_ah[(size_t)M_TOT * EMB]; // A hi (x, later ctx)
__device__ __nv_bfloat16 g_al[(size_t)M_TOT * EMB]; // A lo
__device__ __nv_bfloat16 g_wh[(size_t)4 * EMB * EMB]; // Wq,Wk,Wv,Wo hi
__device__ __nv_bfloat16 g_wl[(size_t)4 * EMB * EMB]; // lo

// ============================================================================
// PTX helpers (sm_80-compatible subset only: cp.async, ldmatrix, mma.sync)
// ============================================================================
__device__ __forceinline__ uint32_t smem_u32(const void* p) {
    uint32_t a;
    asm("{ .reg .u64 t; cvta.to.shared.u64 t, %1; cvt.u32.u64 %0, t; }"
        : "=r"(a) : "l"(p));
    return a;
}
__device__ __forceinline__ void cp16(uint32_t d, const void* s) {
    asm volatile("cp.async.cg.shared.global [%0], [%1], 16;" :: "r"(d), "l"(s));
}
#define CP_COMMIT() asm volatile("cp.async.commit_group;" ::: "memory")
#define CP_WAIT1()  asm volatile("cp.async.wait_group 1;" ::: "memory")

__device__ __forceinline__ void ldsm4(uint32_t* r, uint32_t a) {
    asm volatile("ldmatrix.sync.aligned.m8n8.x4.shared.b16 {%0,%1,%2,%3}, [%4];"
        : "=r"(r[0]), "=r"(r[1]), "=r"(r[2]), "=r"(r[3]) : "r"(a));
}
__device__ __forceinline__ void mma16816(float* d, const uint32_t* a,
                                         uint32_t b0, uint32_t b1) {
    asm volatile(
        "mma.sync.aligned.m16n8k16.row.col.f32.bf16.bf16.f32 "
        "{%0,%1,%2,%3}, {%4,%5,%6,%7}, {%8,%9}, {%0,%1,%2,%3};"
        : "+f"(d[0]), "+f"(d[1]), "+f"(d[2]), "+f"(d[3])
        : "r"(a[0]), "r"(a[1]), "r"(a[2]), "r"(a[3]), "r"(b0), "r"(b1));
}

// ============================================================================
// split fp32 -> bf16 hi + bf16 lo (error compensation)
// ============================================================================
__global__ void split_bf16(const float4* __restrict__ in,
                           __nv_bfloat16* __restrict__ hi,
                           __nv_bfloat16* __restrict__ lo, int n4)
{
    int i = blockIdx.x * blockDim.x + threadIdx.x;
    if (i >= n4) return;
    float4 v = in[i];
    __nv_bfloat16 h0 = __float2bfloat16(v.x);
    __nv_bfloat16 h1 = __float2bfloat16(v.y);
    __nv_bfloat16 h2 = __float2bfloat16(v.z);
    __nv_bfloat16 h3 = __float2bfloat16(v.w);
    __nv_bfloat16 l0 = __float2bfloat16(v.x - __bfloat162float(h0));
    __nv_bfloat16 l1 = __float2bfloat16(v.y - __bfloat162float(h1));
    __nv_bfloat16 l2 = __float2bfloat16(v.z - __bfloat162float(h2));
    __nv_bfloat16 l3 = __float2bfloat16(v.w - __bfloat162float(h3));
    __nv_bfloat162* hp = (__nv_bfloat162*)(hi + (size_t)i * 4);
    __nv_bfloat162* lp = (__nv_bfloat162*)(lo + (size_t)i * 4);
    hp[0] = __halves2bfloat162(h0, h1);
    hp[1] = __halves2bfloat162(h2, h3);
    lp[0] = __halves2bfloat162(l0, l1);
    lp[1] = __halves2bfloat162(l2, l3);
}

// ============================================================================
// HMMA GEMM (NT): C[m][n] = sum_k A[m][k]*B[n][k], fp32 via bf16 hi/lo split.
// CTA tile 128x128, K-chunk 64, 8 warps (each 64x32), double-buffered cp.async.
// Swizzled smem tiles: 128 rows x 128B, chunk16 index xor (row&7).
// MODE 0: C row-major. MODE 1: head layout (B,H,S,D).
// ============================================================================
#define STAGE_BYTES 65536
#define GEMM_SMEM   (2 * STAGE_BYTES)
#define NCH         (EMB / 64)      // 32 K-chunks

template<int MODE>
__global__ void __launch_bounds__(256, 1)
gemm_mma(const __nv_bfloat16* __restrict__ Ah, const __nv_bfloat16* __restrict__ Al,
         const __nv_bfloat16* __restrict__ Bh, const __nv_bfloat16* __restrict__ Bl,
         float* __restrict__ C)
{
    extern __shared__ char smem[];
    const uint32_t sb = smem_u32(smem);
    const int t    = threadIdx.x;
    const int lane = t & 31;
    const int warp = t >> 5;
    const int bn = blockIdx.x, bm = blockIdx.y;

    const int warp_m = warp >> 2;       // 0..1 -> 64 rows each
    const int warp_n = warp & 3;        // 0..3 -> 32 cols each
    const int mbase = warp_m * 64;
    const int nbase = warp_n * 32;

    const char* pAh = (const char*)(Ah + (size_t)bm * 128 * EMB);
    const char* pAl = (const char*)(Al + (size_t)bm * 128 * EMB);
    const char* pBh = (const char*)(Bh + (size_t)bn * 128 * EMB);
    const char* pBl = (const char*)(Bl + (size_t)bn * 128 * EMB);

    // per-thread load coordinates (16B granules)
    const int lrow0 = t >> 3;           // +32 per it
    const int lck   = t & 7;

    float acc[4][4][4];
    #pragma unroll
    for (int i = 0; i < 4; i++)
        #pragma unroll
        for (int j = 0; j < 4; j++)
            #pragma unroll
            for (int c = 0; c < 4; c++) acc[i][j][c] = 0.f;

    // ldmatrix lane addressing pieces
    const int lr16 = lane & 15;         // row within 16
    const int lhalf = lane >> 4;        // 0/1 -> +8 cols (=+1 chunk16)

    // ---- pipeline ----
    // load stage for chunk ch into buffer buf
    auto load_stage = [&](int ch, int buf) {
        const uint32_t st = sb + buf * STAGE_BYTES;
        const size_t cb = (size_t)ch * 128;     // 64 bf16 = 128 bytes along K
        #pragma unroll
        for (int it = 0; it < 4; it++) {
            int row = lrow0 + it * 32;
            uint32_t sw = (uint32_t)(row * 128 + ((lck ^ (row & 7)) << 4));
            size_t go = (size_t)row * (EMB * 2) + cb + lck * 16;
            cp16(st +         sw, pAh + go);
            cp16(st + 16384 + sw, pAl + go);
            cp16(st + 32768 + sw, pBh + go);
            cp16(st + 49152 + sw, pBl + go);
        }
    };

    load_stage(0, 0);
    CP_COMMIT();

    for (int ch = 0; ch < NCH; ch++) {
        if (ch + 1 < NCH) load_stage(ch + 1, (ch + 1) & 1);
        CP_COMMIT();
        CP_WAIT1();
        __syncthreads();

        const uint32_t st = sb + (ch & 1) * STAGE_BYTES;
        const uint32_t stAh = st, stAl = st + 16384, stBh = st + 32768, stBl = st + 49152;

        #pragma unroll
        for (int ks = 0; ks < 4; ks++) {
            const int c16 = ks * 2 + lhalf;
            uint32_t ahf[4][4], alf[4][4], bhf[2][4], blf[2][4];
            #pragma unroll
            for (int mf = 0; mf < 4; mf++) {
                int row = mbase + mf * 16 + lr16;
                uint32_t off = (uint32_t)(row * 128 + ((c16 ^ (row & 7)) << 4));
                ldsm4(ahf[mf], stAh + off);
                ldsm4(alf[mf], stAl + off);
            }
            #pragma unroll
            for (int nf2 = 0; nf2 < 2; nf2++) {
                int row = nbase + nf2 * 16 + lr16;
                uint32_t off = (uint32_t)(row * 128 + ((c16 ^ (row & 7)) << 4));
                ldsm4(bhf[nf2], stBh + off);
                ldsm4(blf[nf2], stBl + off);
            }
            // fragment pairs: n-frag nf uses regs {[nf&1], [(nf&1)+2]} of group nf>>1
            #pragma unroll
            for (int mf = 0; mf < 4; mf++) {
                #pragma unroll
                for (int nf = 0; nf < 4; nf++) {
                    uint32_t bh0 = bhf[nf >> 1][nf & 1], bh1 = bhf[nf >> 1][(nf & 1) + 2];
                    uint32_t bl0 = blf[nf >> 1][nf & 1], bl1 = blf[nf >> 1][(nf & 1) + 2];
                    mma16816(acc[mf][nf], ahf[mf], bh0, bh1);
                    mma16816(acc[mf][nf], ahf[mf], bl0, bl1);
                    mma16816(acc[mf][nf], alf[mf], bh0, bh1);
                }
            }
        }
        __syncthreads();
    }

    // ---- epilogue: direct global float2 stores ----
    const int gid = lane >> 2, qd = lane & 3;
    #pragma unroll
    for (int mf = 0; mf < 4; mf++) {
        #pragma unroll
        for (int half = 0; half < 2; half++) {
            int row_l = mbase + mf * 16 + half * 8 + gid;
            int row   = bm * 128 + row_l;
            float* dst;
            if (MODE == 0) {
                dst = C + (size_t)row * EMB + bn * 128;
            } else {
                int b = row >> 11, s = row & (S_LEN - 1);
                dst = C + (((size_t)(b * NH + bn) * S_LEN + s) << 7);
            }
            #pragma unroll
            for (int nf = 0; nf < 4; nf++) {
                int col_l = nbase + nf * 8 + qd * 2;
                float2 v;
                v.x = acc[mf][nf][half * 2 + 0];
                v.y = acc[mf][nf][half * 2 + 1];
                *(float2*)(dst + col_l) = v;
            }
        }
    }
}

// ============================================================================
// RoPE (unchanged)
// ============================================================================
__global__ void rope_kernel(float* __restrict__ q, const float* __restrict__ kin,
                            float* __restrict__ kout)
{
    int tid = blockIdx.x * blockDim.x + threadIdx.x;
    int dd = tid & 63;
    int s  = (tid >> 6) & (S_LEN - 1);
    int bh = tid >> 17;
    if (bh >= BHN) return;

    float freq = powf(10000.0f, -(float)(2 * dd) / 128.0f);
    float ang  = (float)s * freq;
    float sn, cs;
    sincosf(ang, &sn, &cs);

    size_t base = (((size_t)bh * S_LEN) + s) * HD + dd * 2;
    float x1 = q[base], x2 = q[base + 1];
    q[base]     = x1 * cs - x2 * sn;
    q[base + 1] = x1 * sn + x2 * cs;

    float y1 = kin[base], y2 = kin[base + 1];
    kout[base]     = y1 * cs - y2 * sn;
    kout[base + 1] = y1 * sn + y2 * cs;
}

// ============================================================================
// Flash attention (causal, online softmax), fp32 SIMT (unchanged this round)
// ============================================================================
#define QSTR 68
#define VSTR 132
#define ATT_SMEM ((128*QSTR*2 + 64*VSTR + 64*QSTR) * 4)

__global__ void __launch_bounds__(256, 1)
attn_kernel(const float* __restrict__ Q, const float* __restrict__ Kr,
            const float* __restrict__ V, float* __restrict__ ctx)
{
    extern __shared__ float sm[];
    float* q_t = sm;
    float* k_t = q_t + 128 * QSTR;
    float* v_s = k_t + 128 * QSTR;
    float* s_s = v_s + 64 * VSTR;

    const int t  = threadIdx.x;
    const int qt = blockIdx.x;
    const int bh = blockIdx.y;

    const float* qbase = Q  + ((size_t)bh * S_LEN + qt * 64) * HD;
    const float* kbase = Kr + (size_t)bh * S_LEN * HD;
    const float* vbase = V  + (size_t)bh * S_LEN * HD;

    const int ty = t >> 4, tx = t & 15;
    const int r  = t >> 2, c4 = t & 3;

    #pragma unroll
    for (int it = 0; it < 8; it++) {
        int idx = t + it * 256;
        int rr = idx >> 5;
        int cc = (idx & 31) * 4;
        float4 v4 = *(const float4*)(qbase + (size_t)rr * HD + cc);
        q_t[(cc+0)*QSTR + rr] = v4.x;
        q_t[(cc+1)*QSTR + rr] = v4.y;
        q_t[(cc+2)*QSTR + rr] = v4.z;
        q_t[(cc+3)*QSTR + rr] = v4.w;
    }

    float m_prev = -1e30f, lsum = 0.f;
    float4 acc[8];
    #pragma unroll
    for (int jj = 0; jj < 8; jj++) acc[jj] = make_float4(0.f, 0.f, 0.f, 0.f);

    const float scale = 0.088388347648318447f;

    for (int j = 0; j <= qt; j++) {
        __syncthreads();

        #pragma unroll
        for (int it = 0; it < 8; it++) {
            int idx = t + it * 256;
            int rr = idx >> 5;
            int cc = (idx & 31) * 4;
            float4 kv = *(const float4*)(kbase + (size_t)(j*64 + rr) * HD + cc);
            k_t[(cc+0)*QSTR + rr] = kv.x;
            k_t[(cc+1)*QSTR + rr] = kv.y;
            k_t[(cc+2)*QSTR + rr] = kv.z;
            k_t[(cc+3)*QSTR + rr] = kv.w;
            float4 vv = *(const float4*)(vbase + (size_t)(j*64 + rr) * HD + cc);
            *(float4*)&v_s[rr * VSTR + cc] = vv;
        }
        __syncthreads();

        float racc[4][4];
        #pragma unroll
        for (int i = 0; i < 4; i++)
            #pragma unroll
            for (int jx = 0; jx < 4; jx++) racc[i][jx] = 0.f;

        #pragma unroll 8
        for (int d = 0; d < HD; d++) {
            float4 aq = *(const float4*)&q_t[d*QSTR + ty*4];
            float4 bk = *(const float4*)&k_t[d*QSTR + tx*4];
            float av[4] = {aq.x, aq.y, aq.z, aq.w};
            float bv[4] = {bk.x, bk.y, bk.z, bk.w};
            #pragma unroll
            for (int i = 0; i < 4; i++)
                #pragma unroll
                for (int jx = 0; jx < 4; jx++)
                    racc[i][jx] += av[i] * bv[jx];
        }
        #pragma unroll
        for (int i = 0; i < 4; i++) {
            float4 sv = make_float4(racc[i][0]*scale, racc[i][1]*scale,
                                    racc[i][2]*scale, racc[i][3]*scale);
            *(float4*)&s_s[(ty*4 + i)*QSTR + tx*4] = sv;
        }
        __syncthreads();

        float stmp[16];
        float mloc = -1e30f;
        const bool diag = (j == qt);
        #pragma unroll
        for (int u = 0; u < 16; u++) {
            int col = c4*16 + u;
            float sv = s_s[r*QSTR + col];
            if (diag && col > r) sv = -1e30f;
            stmp[u] = sv;
            mloc = fmaxf(mloc, sv);
        }
        mloc = fmaxf(mloc, __shfl_xor_sync(0xffffffffu, mloc, 1));
        mloc = fmaxf(mloc, __shfl_xor_sync(0xffffffffu, mloc, 2));
        float mnew  = fmaxf(m_prev, mloc);
        float alpha = __expf(m_prev - mnew);
        float lloc = 0.f;
        #pragma unroll
        for (int u = 0; u < 16; u++) {
            float p = __expf(stmp[u] - mnew);
            lloc += p;
            s_s[r*QSTR + c4*16 + u] = p;
        }
        lloc += __shfl_xor_sync(0xffffffffu, lloc, 1);
        lloc += __shfl_xor_sync(0xffffffffu, lloc, 2);
        lsum = lsum * alpha + lloc;
        m_prev = mnew;
        #pragma unroll
        for (int jj = 0; jj < 8; jj++) {
            acc[jj].x *= alpha; acc[jj].y *= alpha;
            acc[jj].z *= alpha; acc[jj].w *= alpha;
        }
        __syncthreads();

        #pragma unroll 4
        for (int kc = 0; kc < 64; kc++) {
            float p = s_s[r*QSTR + kc];
            #pragma unroll
            for (int jj = 0; jj < 8; jj++) {
                float4 vv = *(const float4*)&v_s[kc*VSTR + (c4 + 4*jj)*4];
                acc[jj].x += p * vv.x; acc[jj].y += p * vv.y;
                acc[jj].z += p * vv.z; acc[jj].w += p * vv.w;
            }
        }
    }

    float inv = 1.f / lsum;
    int b = bh >> 4, h = bh & 15;
    float* outp = ctx + ((size_t)b * S_LEN + qt*64 + r) * EMB + h * HD;
    #pragma unroll
    for (int jj = 0; jj < 8; jj++) {
        int d = (c4 + 4*jj) * 4;
        float4 o = make_float4(acc[jj].x*inv, acc[jj].y*inv,
                               acc[jj].z*inv, acc[jj].w*inv);
        *(float4*)(outp + d) = o;
    }
}

// ============================================================================
// launch
// ============================================================================
extern "C" void kernel_launch(void* const* d_in, const int* in_sizes, int n_in,
                              void* d_out, int out_size)
{
    (void)in_sizes; (void)n_in; (void)out_size;
    const float* x  = (const float*)d_in[0];
    const float* Wq = (const float*)d_in[1];
    const float* Wk = (const float*)d_in[2];
    const float* Wv = (const float*)d_in[3];
    const float* Wo = (const float*)d_in[4];

    float* out  = (float*)d_out;
    float* outK = out  + (size_t)NB * S_LEN * EMB;
    float* outV = outK + (size_t)BHN * S_LEN * HD;

    float *qp, *krp, *ctxp;
    __nv_bfloat16 *ah, *al, *wh, *wl;
    cudaGetSymbolAddress((void**)&qp,   g_q);
    cudaGetSymbolAddress((void**)&krp,  g_kr);
    cudaGetSymbolAddress((void**)&ctxp, g_ctx);
    cudaGetSymbolAddress((void**)&ah,   g_ah);
    cudaGetSymbolAddress((void**)&al,   g_al);
    cudaGetSymbolAddress((void**)&wh,   g_wh);
    cudaGetSymbolAddress((void**)&wl,   g_wl);

    cudaFuncSetAttribute(attn_kernel,
                         cudaFuncAttributeMaxDynamicSharedMemorySize, ATT_SMEM);
    cudaFuncSetAttribute(gemm_mma<0>,
                         cudaFuncAttributeMaxDynamicSharedMemorySize, GEMM_SMEM);
    cudaFuncSetAttribute(gemm_mma<1>,
                         cudaFuncAttributeMaxDynamicSharedMemorySize, GEMM_SMEM);

    const size_t woff = (size_t)EMB * EMB;

    // split inputs to bf16 hi/lo
    int n4x = M_TOT * EMB / 4;
    split_bf16<<<(n4x + 255) / 256, 256>>>((const float4*)x, ah, al, n4x);
    int n4w = EMB * EMB / 4;
    split_bf16<<<(n4w + 255) / 256, 256>>>((const float4*)Wq, wh + 0*woff, wl + 0*woff, n4w);
    split_bf16<<<(n4w + 255) / 256, 256>>>((const float4*)Wk, wh + 1*woff, wl + 1*woff, n4w);
    split_bf16<<<(n4w + 255) / 256, 256>>>((const float4*)Wv, wh + 2*woff, wl + 2*woff, n4w);
    split_bf16<<<(n4w + 255) / 256, 256>>>((const float4*)Wo, wh + 3*woff, wl + 3*woff, n4w);

    dim3 gg(EMB / 128, M_TOT / 128);
    gemm_mma<1><<<gg, 256, GEMM_SMEM>>>(ah, al, wh + 0*woff, wl + 0*woff, qp);    // Q
    gemm_mma<1><<<gg, 256, GEMM_SMEM>>>(ah, al, wh + 1*woff, wl + 1*woff, outK);  // K (pre-rope)
    gemm_mma<1><<<gg, 256, GEMM_SMEM>>>(ah, al, wh + 2*woff, wl + 2*woff, outV);  // V

    rope_kernel<<<(BHN * S_LEN * 64) / 256, 256>>>(qp, outK, krp);

    attn_kernel<<<dim3(S_LEN / 64, BHN), 256, ATT_SMEM>>>(qp, krp, outV, ctxp);

    // split ctx (reuse A hi/lo scratch), final projection
    split_bf16<<<(n4x + 255) / 256, 256>>>((const float4*)ctxp, ah, al, n4x);
    gemm_mma<0><<<gg, 256, GEMM_SMEM>>>(ah, al, wh + 3*woff, wl + 3*woff, out);
}

// round 7
// speedup vs baseline: 2.7726x; 1.9308x over previous
#include <cuda_runtime.h>
#include <cuda_bf16.h>
#include <math.h>
#include <stdint.h>

#define S_LEN 2048
#define EMB   2048
#define NB    2
#define NH    16
#define HD    128
#define BHN   (NB*NH)          // 32
#define M_TOT (NB*S_LEN)       // 4096

// -------- scratch (__device__ globals; no allocations allowed) --------
__device__ float g_q  [(size_t)BHN * S_LEN * HD];   // fp32 Q proj (B,H,S,D)
__device__ float g_ctx[(size_t)NB  * S_LEN * EMB];  // attention context, (B,S,E)
__device__ __nv_bfloat16 g_ah[(size_t)M_TOT * EMB]; // A hi (x, later ctx)
__device__ __nv_bfloat16 g_al[(size_t)M_TOT * EMB]; // A lo
__device__ __nv_bfloat16 g_wh[(size_t)4 * EMB * EMB]; // Wq,Wk,Wv,Wo hi
__device__ __nv_bfloat16 g_wl[(size_t)4 * EMB * EMB]; // lo
__device__ __nv_bfloat16 g_qh[(size_t)BHN * S_LEN * HD]; // rope'd Q hi
__device__ __nv_bfloat16 g_ql[(size_t)BHN * S_LEN * HD];
__device__ __nv_bfloat16 g_kh[(size_t)BHN * S_LEN * HD]; // rope'd K hi
__device__ __nv_bfloat16 g_kl[(size_t)BHN * S_LEN * HD];
__device__ __nv_bfloat16 g_vth[(size_t)BHN * HD * S_LEN]; // V^T hi (B,H,D,S)
__device__ __nv_bfloat16 g_vtl[(size_t)BHN * HD * S_LEN];

// ============================================================================
// PTX helpers (sm_80-compatible subset only: cp.async, ldmatrix, mma.sync)
// ============================================================================
__device__ __forceinline__ uint32_t smem_u32(const void* p) {
    uint32_t a;
    asm("{ .reg .u64 t; cvta.to.shared.u64 t, %1; cvt.u32.u64 %0, t; }"
        : "=r"(a) : "l"(p));
    return a;
}
__device__ __forceinline__ void cp16(uint32_t d, const void* s) {
    asm volatile("cp.async.cg.shared.global [%0], [%1], 16;" :: "r"(d), "l"(s));
}
#define CP_COMMIT() asm volatile("cp.async.commit_group;" ::: "memory")
#define CP_WAIT1()  asm volatile("cp.async.wait_group 1;" ::: "memory")
#define CP_WAIT2()  asm volatile("cp.async.wait_group 2;" ::: "memory")

__device__ __forceinline__ void ldsm4(uint32_t* r, uint32_t a) {
    asm volatile("ldmatrix.sync.aligned.m8n8.x4.shared.b16 {%0,%1,%2,%3}, [%4];"
        : "=r"(r[0]), "=r"(r[1]), "=r"(r[2]), "=r"(r[3]) : "r"(a));
}
__device__ __forceinline__ void mma16816(float* d, const uint32_t* a,
                                         uint32_t b0, uint32_t b1) {
    asm volatile(
        "mma.sync.aligned.m16n8k16.row.col.f32.bf16.bf16.f32 "
        "{%0,%1,%2,%3}, {%4,%5,%6,%7}, {%8,%9}, {%0,%1,%2,%3};"
        : "+f"(d[0]), "+f"(d[1]), "+f"(d[2]), "+f"(d[3])
        : "r"(a[0]), "r"(a[1]), "r"(a[2]), "r"(a[3]), "r"(b0), "r"(b1));
}
__device__ __forceinline__ uint32_t pack_bf16x2(float a, float b) {
    __nv_bfloat162 v = __halves2bfloat162(__float2bfloat16(a), __float2bfloat16(b));
    return *(uint32_t*)&v;
}

// ============================================================================
// split fp32 -> bf16 hi + bf16 lo
// ============================================================================
__global__ void split_bf16(const float4* __restrict__ in,
                           __nv_bfloat16* __restrict__ hi,
                           __nv_bfloat16* __restrict__ lo, int n4)
{
    int i = blockIdx.x * blockDim.x + threadIdx.x;
    if (i >= n4) return;
    float4 v = in[i];
    __nv_bfloat16 h0 = __float2bfloat16(v.x);
    __nv_bfloat16 h1 = __float2bfloat16(v.y);
    __nv_bfloat16 h2 = __float2bfloat16(v.z);
    __nv_bfloat16 h3 = __float2bfloat16(v.w);
    __nv_bfloat16 l0 = __float2bfloat16(v.x - __bfloat162float(h0));
    __nv_bfloat16 l1 = __float2bfloat16(v.y - __bfloat162float(h1));
    __nv_bfloat16 l2 = __float2bfloat16(v.z - __bfloat162float(h2));
    __nv_bfloat16 l3 = __float2bfloat16(v.w - __bfloat162float(h3));
    __nv_bfloat162* hp = (__nv_bfloat162*)(hi + (size_t)i * 4);
    __nv_bfloat162* lp = (__nv_bfloat162*)(lo + (size_t)i * 4);
    hp[0] = __halves2bfloat162(h0, h1);
    hp[1] = __halves2bfloat162(h2, h3);
    lp[0] = __halves2bfloat162(l0, l1);
    lp[1] = __halves2bfloat162(l2, l3);
}

// ============================================================================
// HMMA GEMM (NT), 3-stage cp.async pipeline. Tile 128x128, K-chunk 64.
// MODE 0: C row-major. MODE 1: head layout (B,H,S,D).
// ============================================================================
#define STAGE_BYTES 65536
#define GEMM_SMEM   (3 * STAGE_BYTES)
#define NCH         (EMB / 64)      // 32 K-chunks

template<int MODE>
__global__ void __launch_bounds__(256, 1)
gemm_mma(const __nv_bfloat16* __restrict__ Ah, const __nv_bfloat16* __restrict__ Al,
         const __nv_bfloat16* __restrict__ Bh, const __nv_bfloat16* __restrict__ Bl,
         float* __restrict__ C)
{
    extern __shared__ char smem[];
    const uint32_t sb = smem_u32(smem);
    const int t    = threadIdx.x;
    const int lane = t & 31;
    const int warp = t >> 5;
    const int bn = blockIdx.x, bm = blockIdx.y;

    const int warp_m = warp >> 2;
    const int warp_n = warp & 3;
    const int mbase = warp_m * 64;
    const int nbase = warp_n * 32;

    const char* pAh = (const char*)(Ah + (size_t)bm * 128 * EMB);
    const char* pAl = (const char*)(Al + (size_t)bm * 128 * EMB);
    const char* pBh = (const char*)(Bh + (size_t)bn * 128 * EMB);
    const char* pBl = (const char*)(Bl + (size_t)bn * 128 * EMB);

    const int lrow0 = t >> 3;
    const int lck   = t & 7;

    float acc[4][4][4];
    #pragma unroll
    for (int i = 0; i < 4; i++)
        #pragma unroll
        for (int j = 0; j < 4; j++)
            #pragma unroll
            for (int c = 0; c < 4; c++) acc[i][j][c] = 0.f;

    const int lr16 = lane & 15;
    const int lhalf = lane >> 4;

    auto load_stage = [&](int ch, int buf) {
        const uint32_t st = sb + buf * STAGE_BYTES;
        const size_t cb = (size_t)ch * 128;
        #pragma unroll
        for (int it = 0; it < 4; it++) {
            int row = lrow0 + it * 32;
            uint32_t sw = (uint32_t)(row * 128 + ((lck ^ (row & 7)) << 4));
            size_t go = (size_t)row * (EMB * 2) + cb + lck * 16;
            cp16(st +         sw, pAh + go);
            cp16(st + 16384 + sw, pAl + go);
            cp16(st + 32768 + sw, pBh + go);
            cp16(st + 49152 + sw, pBl + go);
        }
    };

    load_stage(0, 0);
    CP_COMMIT();
    load_stage(1, 1);
    CP_COMMIT();

    for (int ch = 0; ch < NCH; ch++) {
        if (ch + 2 < NCH) load_stage(ch + 2, (ch + 2) % 3);
        CP_COMMIT();
        CP_WAIT2();
        __syncthreads();

        const uint32_t st = sb + (ch % 3) * STAGE_BYTES;
        const uint32_t stAh = st, stAl = st + 16384, stBh = st + 32768, stBl = st + 49152;

        #pragma unroll
        for (int ks = 0; ks < 4; ks++) {
            const int c16 = ks * 2 + lhalf;
            uint32_t ahf[4][4], alf[4][4], bhf[2][4], blf[2][4];
            #pragma unroll
            for (int mf = 0; mf < 4; mf++) {
                int row = mbase + mf * 16 + lr16;
                uint32_t off = (uint32_t)(row * 128 + ((c16 ^ (row & 7)) << 4));
                ldsm4(ahf[mf], stAh + off);
                ldsm4(alf[mf], stAl + off);
            }
            #pragma unroll
            for (int nf2 = 0; nf2 < 2; nf2++) {
                int row = nbase + nf2 * 16 + lr16;
                uint32_t off = (uint32_t)(row * 128 + ((c16 ^ (row & 7)) << 4));
                ldsm4(bhf[nf2], stBh + off);
                ldsm4(blf[nf2], stBl + off);
            }
            #pragma unroll
            for (int mf = 0; mf < 4; mf++) {
                #pragma unroll
                for (int nf = 0; nf < 4; nf++) {
                    uint32_t bh0 = bhf[nf >> 1][nf & 1], bh1 = bhf[nf >> 1][(nf & 1) + 2];
                    uint32_t bl0 = blf[nf >> 1][nf & 1], bl1 = blf[nf >> 1][(nf & 1) + 2];
                    mma16816(acc[mf][nf], ahf[mf], bh0, bh1);
                    mma16816(acc[mf][nf], ahf[mf], bl0, bl1);
                    mma16816(acc[mf][nf], alf[mf], bh0, bh1);
                }
            }
        }
        __syncthreads();
    }

    const int gid = lane >> 2, qd = lane & 3;
    #pragma unroll
    for (int mf = 0; mf < 4; mf++) {
        #pragma unroll
        for (int half = 0; half < 2; half++) {
            int row_l = mbase + mf * 16 + half * 8 + gid;
            int row   = bm * 128 + row_l;
            float* dst;
            if (MODE == 0) {
                dst = C + (size_t)row * EMB + bn * 128;
            } else {
                int b = row >> 11, s = row & (S_LEN - 1);
                dst = C + (((size_t)(b * NH + bn) * S_LEN + s) << 7);
            }
            #pragma unroll
            for (int nf = 0; nf < 4; nf++) {
                int col_l = nbase + nf * 8 + qd * 2;
                float2 v;
                v.x = acc[mf][nf][half * 2 + 0];
                v.y = acc[mf][nf][half * 2 + 1];
                *(float2*)(dst + col_l) = v;
            }
        }
    }
}

// ============================================================================
// RoPE + split to bf16 hi/lo: q fp32 -> qh/ql, k fp32 -> kh/kl
// ============================================================================
__global__ void rope_split(const float* __restrict__ q, const float* __restrict__ kin,
                           __nv_bfloat16* __restrict__ qh, __nv_bfloat16* __restrict__ ql,
                           __nv_bfloat16* __restrict__ kh, __nv_bfloat16* __restrict__ kl)
{
    int tid = blockIdx.x * blockDim.x + threadIdx.x;
    int dd = tid & 63;
    int s  = (tid >> 6) & (S_LEN - 1);
    int bh = tid >> 17;
    if (bh >= BHN) return;

    float freq = powf(10000.0f, -(float)(2 * dd) / 128.0f);
    float ang  = (float)s * freq;
    float sn, cs;
    sincosf(ang, &sn, &cs);

    size_t base = (((size_t)bh * S_LEN) + s) * HD + dd * 2;
    float x1 = q[base], x2 = q[base + 1];
    float q1 = x1 * cs - x2 * sn;
    float q2 = x1 * sn + x2 * cs;
    float y1 = kin[base], y2 = kin[base + 1];
    float k1 = y1 * cs - y2 * sn;
    float k2 = y1 * sn + y2 * cs;

    __nv_bfloat16 qh1 = __float2bfloat16(q1), qh2 = __float2bfloat16(q2);
    __nv_bfloat16 kh1 = __float2bfloat16(k1), kh2 = __float2bfloat16(k2);
    *(__nv_bfloat162*)(qh + base) = __halves2bfloat162(qh1, qh2);
    *(__nv_bfloat162*)(ql + base) = __halves2bfloat162(
        __float2bfloat16(q1 - __bfloat162float(qh1)),
        __float2bfloat16(q2 - __bfloat162float(qh2)));
    *(__nv_bfloat162*)(kh + base) = __halves2bfloat162(kh1, kh2);
    *(__nv_bfloat162*)(kl + base) = __halves2bfloat162(
        __float2bfloat16(k1 - __bfloat162float(kh1)),
        __float2bfloat16(k2 - __bfloat162float(kh2)));
}

// ============================================================================
// V transpose + split: (B,H,S,D) fp32 -> (B,H,D,S) bf16 hi/lo
// ============================================================================
__global__ void vsplit_t(const float* __restrict__ v,
                         __nv_bfloat16* __restrict__ vth, __nv_bfloat16* __restrict__ vtl)
{
    __shared__ float tile[32][33];
    int tx = threadIdx.x, ty = threadIdx.y;     // block (32, 8)
    int s0 = blockIdx.x * 32, d0 = blockIdx.y * 32, bh = blockIdx.z;

    #pragma unroll
    for (int k = 0; k < 4; k++) {
        int s = s0 + ty + k * 8;
        tile[ty + k * 8][tx] = v[((size_t)bh * S_LEN + s) * HD + d0 + tx];
    }
    __syncthreads();
    #pragma unroll
    for (int k = 0; k < 4; k++) {
        int d = d0 + ty + k * 8;
        float x = tile[tx][ty + k * 8];
        __nv_bfloat16 h = __float2bfloat16(x);
        size_t o = ((size_t)bh * HD + d) * S_LEN + s0 + tx;
        vth[o] = h;
        vtl[o] = __float2bfloat16(x - __bfloat162float(h));
    }
}

// ============================================================================
// HMMA flash attention (causal). BM=128, BN=64, D=128, 8 warps.
// Q/K bf16 hi/lo (B,H,S,D); V^T bf16 hi/lo (B,H,D,S). 3-term everywhere.
// smem: Qh[0,32K) Ql[32K,64K) | K stages 64K+buf*32K (Kh 16K, Kl 16K)
//       | V stages 128K+buf*32K (Vh 16K, Vl 16K).  Total 192K.
// ============================================================================
#define SK_OFF 65536
#define SV_OFF 131072
#define ATT_SMEM 196608

__global__ void __launch_bounds__(256, 1)
attn_mma(const __nv_bfloat16* __restrict__ qh, const __nv_bfloat16* __restrict__ ql,
         const __nv_bfloat16* __restrict__ kh, const __nv_bfloat16* __restrict__ kl,
         const __nv_bfloat16* __restrict__ vth, const __nv_bfloat16* __restrict__ vtl,
         float* __restrict__ ctx)
{
    extern __shared__ char smem[];
    const uint32_t sb = smem_u32(smem);
    const int t    = threadIdx.x;
    const int lane = t & 31;
    const int w    = t >> 5;
    const int qt   = (int)gridDim.x - 1 - (int)blockIdx.x;   // heavy tiles first
    const int bh   = blockIdx.y;

    const int lr16  = lane & 15;
    const int lhalf = lane >> 4;
    const int gid   = lane >> 2;   // row within 8
    const int qd    = lane & 3;    // col pair selector

    // ---- load Q tile (128 x 128 bf16, hi+lo), once ----
    #pragma unroll
    for (int it = 0; it < 8; it++) {
        int idx = t + it * 256;
        int row = idx >> 4, c = idx & 15;
        uint32_t sw = (uint32_t)(row * 256 + ((c ^ (row & 7)) << 4));
        size_t gq = (((size_t)bh * S_LEN) + qt * 128 + row) * HD + c * 8;
        cp16(sb +         sw, qh + gq);
        cp16(sb + 32768 + sw, ql + gq);
    }

    auto load_kv = [&](int j, int buf) {
        const uint32_t stK = sb + SK_OFF + buf * 32768;
        const uint32_t stV = sb + SV_OFF + buf * 32768;
        #pragma unroll
        for (int it = 0; it < 4; it++) {
            int idx = t + it * 256;
            int rowK = idx >> 4, cK = idx & 15;
            uint32_t swK = (uint32_t)(rowK * 256 + ((cK ^ (rowK & 7)) << 4));
            size_t gk = (((size_t)bh * S_LEN) + j * 64 + rowK) * HD + cK * 8;
            cp16(stK +         swK, kh + gk);
            cp16(stK + 16384 + swK, kl + gk);
            int rowV = idx >> 3, cV = idx & 7;
            uint32_t swV = (uint32_t)(rowV * 128 + ((cV ^ (rowV & 7)) << 4));
            size_t gv = (((size_t)bh * HD) + rowV) * S_LEN + j * 64 + cV * 8;
            cp16(stV +         swV, vth + gv);
            cp16(stV + 16384 + swV, vtl + gv);
        }
    };

    load_kv(0, 0);
    CP_COMMIT();

    float oacc[16][4];
    #pragma unroll
    for (int i = 0; i < 16; i++)
        #pragma unroll
        for (int c = 0; c < 4; c++) oacc[i][c] = 0.f;
    float mp0 = -1e30f, mp1 = -1e30f, ls0 = 0.f, ls1 = 0.f;

    const float scale = 0.088388347648318447f;  // 1/sqrt(128)
    const int jmax = 2 * qt + 1;
    const int row0g = qt * 128 + w * 16 + gid;  // global q row (thread's row 0)
    const int row1g = row0g + 8;

    for (int j = 0; j <= jmax; j++) {
        if (j + 1 <= jmax) load_kv(j + 1, (j + 1) & 1);
        CP_COMMIT();
        CP_WAIT1();
        __syncthreads();

        const uint32_t stKh = sb + SK_OFF + (j & 1) * 32768;
        const uint32_t stKl = stKh + 16384;
        const uint32_t stVh = sb + SV_OFF + (j & 1) * 32768;
        const uint32_t stVl = stVh + 16384;

        // ---- S = Q K^T (warp: 16 rows x 64 cols) ----
        float sacc[8][4];
        #pragma unroll
        for (int i = 0; i < 8; i++)
            #pragma unroll
            for (int c = 0; c < 4; c++) sacc[i][c] = 0.f;

        #pragma unroll
        for (int kd = 0; kd < 8; kd++) {
            const int c16 = kd * 2 + lhalf;
            int rowA = w * 16 + lr16;
            uint32_t offA = (uint32_t)(rowA * 256 + ((c16 ^ (rowA & 7)) << 4));
            uint32_t ah4[4], al4[4];
            ldsm4(ah4, sb +         offA);
            ldsm4(al4, sb + 32768 + offA);
            #pragma unroll
            for (int nb = 0; nb < 4; nb++) {
                int rowB = nb * 16 + lr16;
                uint32_t offB = (uint32_t)(rowB * 256 + ((c16 ^ (rowB & 7)) << 4));
                uint32_t bh4[4], bl4[4];
                ldsm4(bh4, stKh + offB);
                ldsm4(bl4, stKl + offB);
                mma16816(sacc[2*nb],   ah4, bh4[0], bh4[2]);
                mma16816(sacc[2*nb],   ah4, bl4[0], bl4[2]);
                mma16816(sacc[2*nb],   al4, bh4[0], bh4[2]);
                mma16816(sacc[2*nb+1], ah4, bh4[1], bh4[3]);
                mma16816(sacc[2*nb+1], ah4, bl4[1], bl4[3]);
                mma16816(sacc[2*nb+1], al4, bh4[1], bh4[3]);
            }
        }

        // ---- online softmax (registers) ----
        const bool need_mask = (j * 64 + 63) > (qt * 128 + w * 16);
        float mx0 = -1e30f, mx1 = -1e30f;
        #pragma unroll
        for (int nf = 0; nf < 8; nf++) {
            int colg = j * 64 + nf * 8 + qd * 2;
            float v0 = sacc[nf][0] * scale;
            float v1 = sacc[nf][1] * scale;
            float v2 = sacc[nf][2] * scale;
            float v3 = sacc[nf][3] * scale;
            if (need_mask) {
                if (colg     > row0g) v0 = -1e30f;
                if (colg + 1 > row0g) v1 = -1e30f;
                if (colg     > row1g) v2 = -1e30f;
                if (colg + 1 > row1g) v3 = -1e30f;
            }
            sacc[nf][0] = v0; sacc[nf][1] = v1; sacc[nf][2] = v2; sacc[nf][3] = v3;
            mx0 = fmaxf(mx0, fmaxf(v0, v1));
            mx1 = fmaxf(mx1, fmaxf(v2, v3));
        }
        mx0 = fmaxf(mx0, __shfl_xor_sync(0xffffffffu, mx0, 1));
        mx0 = fmaxf(mx0, __shfl_xor_sync(0xffffffffu, mx0, 2));
        mx1 = fmaxf(mx1, __shfl_xor_sync(0xffffffffu, mx1, 1));
        mx1 = fmaxf(mx1, __shfl_xor_sync(0xffffffffu, mx1, 2));
        float mn0 = fmaxf(mp0, mx0), mn1 = fmaxf(mp1, mx1);
        float a0 = __expf(mp0 - mn0), a1 = __expf(mp1 - mn1);
        mp0 = mn0; mp1 = mn1;
        float pl0 = 0.f, pl1 = 0.f;
        #pragma unroll
        for (int nf = 0; nf < 8; nf++) {
            float p0 = __expf(sacc[nf][0] - mn0);
            float p1 = __expf(sacc[nf][1] - mn0);
            float p2 = __expf(sacc[nf][2] - mn1);
            float p3 = __expf(sacc[nf][3] - mn1);
            sacc[nf][0] = p0; sacc[nf][1] = p1; sacc[nf][2] = p2; sacc[nf][3] = p3;
            pl0 += p0 + p1; pl1 += p2 + p3;
        }
        ls0 = ls0 * a0 + pl0;
        ls1 = ls1 * a1 + pl1;
        #pragma unroll
        for (int nf = 0; nf < 16; nf++) {
            oacc[nf][0] *= a0; oacc[nf][1] *= a0;
            oacc[nf][2] *= a1; oacc[nf][3] *= a1;
        }

        // ---- O += P V  (P from registers, V^T as NT B operand) ----
        #pragma unroll
        for (int ks = 0; ks < 4; ks++) {
            uint32_t pa[4], pb[4];
            {
                float p00 = sacc[2*ks][0],   p01 = sacc[2*ks][1];
                float p02 = sacc[2*ks][2],   p03 = sacc[2*ks][3];
                float p10 = sacc[2*ks+1][0], p11 = sacc[2*ks+1][1];
                float p12 = sacc[2*ks+1][2], p13 = sacc[2*ks+1][3];
                pa[0] = pack_bf16x2(p00, p01);
                pa[1] = pack_bf16x2(p02, p03);
                pa[2] = pack_bf16x2(p10, p11);
                pa[3] = pack_bf16x2(p12, p13);
                __nv_bfloat162 h;
                h = *(__nv_bfloat162*)&pa[0];
                pb[0] = pack_bf16x2(p00 - __bfloat162float(h.x), p01 - __bfloat162float(h.y));
                h = *(__nv_bfloat162*)&pa[1];
                pb[1] = pack_bf16x2(p02 - __bfloat162float(h.x), p03 - __bfloat162float(h.y));
                h = *(__nv_bfloat162*)&pa[2];
                pb[2] = pack_bf16x2(p10 - __bfloat162float(h.x), p11 - __bfloat162float(h.y));
                h = *(__nv_bfloat162*)&pa[3];
                pb[3] = pack_bf16x2(p12 - __bfloat162float(h.x), p13 - __bfloat162float(h.y));
            }
            const int c16 = ks * 2 + lhalf;
            #pragma unroll
            for (int nb = 0; nb < 8; nb++) {
                int rowB = nb * 16 + lr16;
                uint32_t offB = (uint32_t)(rowB * 128 + ((c16 ^ (rowB & 7)) << 4));
                uint32_t vh4[4], vl4[4];
                ldsm4(vh4, stVh + offB);
                ldsm4(vl4, stVl + offB);
                mma16816(oacc[2*nb],   pa, vh4[0], vh4[2]);
                mma16816(oacc[2*nb],   pa, vl4[0], vl4[2]);
                mma16816(oacc[2*nb],   pb, vh4[0], vh4[2]);
                mma16816(oacc[2*nb+1], pa, vh4[1], vh4[3]);
                mma16816(oacc[2*nb+1], pa, vl4[1], vl4[3]);
                mma16816(oacc[2*nb+1], pb, vh4[1], vh4[3]);
            }
        }
        __syncthreads();
    }

    // ---- finalize + write ctx (B,S,E) ----
    ls0 += __shfl_xor_sync(0xffffffffu, ls0, 1);
    ls0 += __shfl_xor_sync(0xffffffffu, ls0, 2);
    ls1 += __shfl_xor_sync(0xffffffffu, ls1, 1);
    ls1 += __shfl_xor_sync(0xffffffffu, ls1, 2);
    float rn0 = 1.f / ls0, rn1 = 1.f / ls1;

    int b = bh >> 4, h = bh & 15;
    float* o0 = ctx + ((size_t)b * S_LEN + row0g) * EMB + h * HD;
    float* o1 = o0 + (size_t)8 * EMB;
    #pragma unroll
    for (int nf = 0; nf < 16; nf++) {
        int col = nf * 8 + qd * 2;
        float2 v0 = make_float2(oacc[nf][0] * rn0, oacc[nf][1] * rn0);
        float2 v1 = make_float2(oacc[nf][2] * rn1, oacc[nf][3] * rn1);
        *(float2*)(o0 + col) = v0;
        *(float2*)(o1 + col) = v1;
    }
}

// ============================================================================
// launch
// ============================================================================
extern "C" void kernel_launch(void* const* d_in, const int* in_sizes, int n_in,
                              void* d_out, int out_size)
{
    (void)in_sizes; (void)n_in; (void)out_size;
    const float* x  = (const float*)d_in[0];
    const float* Wq = (const float*)d_in[1];
    const float* Wk = (const float*)d_in[2];
    const float* Wv = (const float*)d_in[3];
    const float* Wo = (const float*)d_in[4];

    float* out  = (float*)d_out;
    float* outK = out  + (size_t)NB * S_LEN * EMB;
    float* outV = outK + (size_t)BHN * S_LEN * HD;

    float *qp, *ctxp;
    __nv_bfloat16 *ah, *al, *wh, *wl, *qhp, *qlp, *khp, *klp, *vthp, *vtlp;
    cudaGetSymbolAddress((void**)&qp,   g_q);
    cudaGetSymbolAddress((void**)&ctxp, g_ctx);
    cudaGetSymbolAddress((void**)&ah,   g_ah);
    cudaGetSymbolAddress((void**)&al,   g_al);
    cudaGetSymbolAddress((void**)&wh,   g_wh);
    cudaGetSymbolAddress((void**)&wl,   g_wl);
    cudaGetSymbolAddress((void**)&qhp,  g_qh);
    cudaGetSymbolAddress((void**)&qlp,  g_ql);
    cudaGetSymbolAddress((void**)&khp,  g_kh);
    cudaGetSymbolAddress((void**)&klp,  g_kl);
    cudaGetSymbolAddress((void**)&vthp, g_vth);
    cudaGetSymbolAddress((void**)&vtlp, g_vtl);

    cudaFuncSetAttribute(attn_mma,
                         cudaFuncAttributeMaxDynamicSharedMemorySize, ATT_SMEM);
    cudaFuncSetAttribute(gemm_mma<0>,
                         cudaFuncAttributeMaxDynamicSharedMemorySize, GEMM_SMEM);
    cudaFuncSetAttribute(gemm_mma<1>,
                         cudaFuncAttributeMaxDynamicSharedMemorySize, GEMM_SMEM);

    const size_t woff = (size_t)EMB * EMB;

    int n4x = M_TOT * EMB / 4;
    split_bf16<<<(n4x + 255) / 256, 256>>>((const float4*)x, ah, al, n4x);
    int n4w = EMB * EMB / 4;
    split_bf16<<<(n4w + 255) / 256, 256>>>((const float4*)Wq, wh + 0*woff, wl + 0*woff, n4w);
    split_bf16<<<(n4w + 255) / 256, 256>>>((const float4*)Wk, wh + 1*woff, wl + 1*woff, n4w);
    split_bf16<<<(n4w + 255) / 256, 256>>>((const float4*)Wv, wh + 2*woff, wl + 2*woff, n4w);
    split_bf16<<<(n4w + 255) / 256, 256>>>((const float4*)Wo, wh + 3*woff, wl + 3*woff, n4w);

    dim3 gg(EMB / 128, M_TOT / 128);
    gemm_mma<1><<<gg, 256, GEMM_SMEM>>>(ah, al, wh + 0*woff, wl + 0*woff, qp);    // Q
    gemm_mma<1><<<gg, 256, GEMM_SMEM>>>(ah, al, wh + 1*woff, wl + 1*woff, outK);  // K (pre-rope)
    gemm_mma<1><<<gg, 256, GEMM_SMEM>>>(ah, al, wh + 2*woff, wl + 2*woff, outV);  // V

    rope_split<<<(BHN * S_LEN * 64) / 256, 256>>>(qp, outK, qhp, qlp, khp, klp);
    vsplit_t<<<dim3(S_LEN / 32, HD / 32, BHN), dim3(32, 8)>>>(outV, vthp, vtlp);

    attn_mma<<<dim3(S_LEN / 128, BHN), 256, ATT_SMEM>>>(qhp, qlp, khp, klp,
                                                        vthp, vtlp, ctxp);

    split_bf16<<<(n4x + 255) / 256, 256>>>((const float4*)ctxp, ah, al, n4x);
    gemm_mma<0><<<gg, 256, GEMM_SMEM>>>(ah, al, wh + 3*woff, wl + 3*woff, out);
}

// round 8
// speedup vs baseline: 2.9041x; 1.0474x over previous
#include <cuda_runtime.h>
#include <cuda_bf16.h>
#include <math.h>
#include <stdint.h>

#define S_LEN 2048
#define EMB   2048
#define NB    2
#define NH    16
#define HD    128
#define BHN   (NB*NH)          // 32
#define M_TOT (NB*S_LEN)       // 4096

// -------- scratch (__device__ globals; no allocations allowed) --------
__device__ __nv_bfloat16 g_ah[(size_t)M_TOT * EMB]; // A hi (x, later ctx)
__device__ __nv_bfloat16 g_al[(size_t)M_TOT * EMB]; // A lo
__device__ __nv_bfloat16 g_wh[(size_t)4 * EMB * EMB]; // Wq,Wk,Wv,Wo hi
__device__ __nv_bfloat16 g_wl[(size_t)4 * EMB * EMB]; // lo
__device__ __nv_bfloat16 g_qh[(size_t)BHN * S_LEN * HD]; // rope'd Q hi
__device__ __nv_bfloat16 g_ql[(size_t)BHN * S_LEN * HD];
__device__ __nv_bfloat16 g_kh[(size_t)BHN * S_LEN * HD]; // rope'd K hi
__device__ __nv_bfloat16 g_kl[(size_t)BHN * S_LEN * HD];
__device__ __nv_bfloat16 g_vth[(size_t)BHN * HD * S_LEN]; // V^T hi (B,H,D,S)
__device__ __nv_bfloat16 g_vtl[(size_t)BHN * HD * S_LEN];

// ============================================================================
// PTX helpers (sm_80-compatible subset only: cp.async, ldmatrix, mma.sync)
// ============================================================================
__device__ __forceinline__ uint32_t smem_u32(const void* p) {
    uint32_t a;
    asm("{ .reg .u64 t; cvta.to.shared.u64 t, %1; cvt.u32.u64 %0, t; }"
        : "=r"(a) : "l"(p));
    return a;
}
__device__ __forceinline__ void cp16(uint32_t d, const void* s) {
    asm volatile("cp.async.cg.shared.global [%0], [%1], 16;" :: "r"(d), "l"(s));
}
#define CP_COMMIT() asm volatile("cp.async.commit_group;" ::: "memory")
#define CP_WAIT1()  asm volatile("cp.async.wait_group 1;" ::: "memory")
#define CP_WAIT2()  asm volatile("cp.async.wait_group 2;" ::: "memory")

__device__ __forceinline__ void ldsm4(uint32_t* r, uint32_t a) {
    asm volatile("ldmatrix.sync.aligned.m8n8.x4.shared.b16 {%0,%1,%2,%3}, [%4];"
        : "=r"(r[0]), "=r"(r[1]), "=r"(r[2]), "=r"(r[3]) : "r"(a));
}
__device__ __forceinline__ void mma16816(float* d, const uint32_t* a,
                                         uint32_t b0, uint32_t b1) {
    asm volatile(
        "mma.sync.aligned.m16n8k16.row.col.f32.bf16.bf16.f32 "
        "{%0,%1,%2,%3}, {%4,%5,%6,%7}, {%8,%9}, {%0,%1,%2,%3};"
        : "+f"(d[0]), "+f"(d[1]), "+f"(d[2]), "+f"(d[3])
        : "r"(a[0]), "r"(a[1]), "r"(a[2]), "r"(a[3]), "r"(b0), "r"(b1));
}
__device__ __forceinline__ uint32_t pack_bf16x2(float a, float b) {
    __nv_bfloat162 v = __halves2bfloat162(__float2bfloat16(a), __float2bfloat16(b));
    return *(uint32_t*)&v;
}
__device__ __forceinline__ void split_store(__nv_bfloat16* hi, __nv_bfloat16* lo,
                                            size_t off, float a, float b) {
    __nv_bfloat16 h0 = __float2bfloat16(a), h1 = __float2bfloat16(b);
    *(__nv_bfloat162*)(hi + off) = __halves2bfloat162(h0, h1);
    *(__nv_bfloat162*)(lo + off) = __halves2bfloat162(
        __float2bfloat16(a - __bfloat162float(h0)),
        __float2bfloat16(b - __bfloat162float(h1)));
}

// ============================================================================
// split fp32 -> bf16 hi + bf16 lo (x and the 4 weights)
// ============================================================================
__global__ void split_bf16(const float4* __restrict__ in,
                           __nv_bfloat16* __restrict__ hi,
                           __nv_bfloat16* __restrict__ lo, int n4)
{
    int i = blockIdx.x * blockDim.x + threadIdx.x;
    if (i >= n4) return;
    float4 v = in[i];
    __nv_bfloat16 h0 = __float2bfloat16(v.x);
    __nv_bfloat16 h1 = __float2bfloat16(v.y);
    __nv_bfloat16 h2 = __float2bfloat16(v.z);
    __nv_bfloat16 h3 = __float2bfloat16(v.w);
    __nv_bfloat162* hp = (__nv_bfloat162*)(hi + (size_t)i * 4);
    __nv_bfloat162* lp = (__nv_bfloat162*)(lo + (size_t)i * 4);
    hp[0] = __halves2bfloat162(h0, h1);
    hp[1] = __halves2bfloat162(h2, h3);
    lp[0] = __halves2bfloat162(__float2bfloat16(v.x - __bfloat162float(h0)),
                               __float2bfloat16(v.y - __bfloat162float(h1)));
    lp[1] = __halves2bfloat162(__float2bfloat16(v.z - __bfloat162float(h2)),
                               __float2bfloat16(v.w - __bfloat162float(h3)));
}

// ============================================================================
// HMMA GEMM cores (NT), 3-stage cp.async pipeline. Tile 128x128, K-chunk 64.
// ============================================================================
#define STAGE_BYTES 65536
#define GEMM_SMEM   (3 * STAGE_BYTES)
#define NCH         (EMB / 64)      // 32 K-chunks

struct GemmCtx {
    float acc[4][4][4];
    int mbase, nbase, lr16, lhalf, lrow0, lck;
};

__device__ __forceinline__ void gemm_mainloop(
    GemmCtx& g, uint32_t sb,
    const char* pAh, const char* pAl, const char* pBh, const char* pBl)
{
    #pragma unroll
    for (int i = 0; i < 4; i++)
        #pragma unroll
        for (int j = 0; j < 4; j++)
            #pragma unroll
            for (int c = 0; c < 4; c++) g.acc[i][j][c] = 0.f;

    auto load_stage = [&](int ch, int buf) {
        const uint32_t st = sb + buf * STAGE_BYTES;
        const size_t cb = (size_t)ch * 128;
        #pragma unroll
        for (int it = 0; it < 4; it++) {
            int row = g.lrow0 + it * 32;
            uint32_t sw = (uint32_t)(row * 128 + ((g.lck ^ (row & 7)) << 4));
            size_t go = (size_t)row * (EMB * 2) + cb + g.lck * 16;
            cp16(st +         sw, pAh + go);
            cp16(st + 16384 + sw, pAl + go);
            cp16(st + 32768 + sw, pBh + go);
            cp16(st + 49152 + sw, pBl + go);
        }
    };

    load_stage(0, 0);
    CP_COMMIT();
    load_stage(1, 1);
    CP_COMMIT();

    for (int ch = 0; ch < NCH; ch++) {
        if (ch + 2 < NCH) load_stage(ch + 2, (ch + 2) % 3);
        CP_COMMIT();
        CP_WAIT2();
        __syncthreads();

        const uint32_t st = sb + (ch % 3) * STAGE_BYTES;
        const uint32_t stAh = st, stAl = st + 16384, stBh = st + 32768, stBl = st + 49152;

        #pragma unroll
        for (int ks = 0; ks < 4; ks++) {
            const int c16 = ks * 2 + g.lhalf;
            uint32_t ahf[4][4], alf[4][4], bhf[2][4], blf[2][4];
            #pragma unroll
            for (int mf = 0; mf < 4; mf++) {
                int row = g.mbase + mf * 16 + g.lr16;
                uint32_t off = (uint32_t)(row * 128 + ((c16 ^ (row & 7)) << 4));
                ldsm4(ahf[mf], stAh + off);
                ldsm4(alf[mf], stAl + off);
            }
            #pragma unroll
            for (int nf2 = 0; nf2 < 2; nf2++) {
                int row = g.nbase + nf2 * 16 + g.lr16;
                uint32_t off = (uint32_t)(row * 128 + ((c16 ^ (row & 7)) << 4));
                ldsm4(bhf[nf2], stBh + off);
                ldsm4(blf[nf2], stBl + off);
            }
            #pragma unroll
            for (int mf = 0; mf < 4; mf++) {
                #pragma unroll
                for (int nf = 0; nf < 4; nf++) {
                    uint32_t b0 = bhf[nf >> 1][nf & 1], b1 = bhf[nf >> 1][(nf & 1) + 2];
                    uint32_t l0 = blf[nf >> 1][nf & 1], l1 = blf[nf >> 1][(nf & 1) + 2];
                    mma16816(g.acc[mf][nf], ahf[mf], b0, b1);
                    mma16816(g.acc[mf][nf], ahf[mf], l0, l1);
                    mma16816(g.acc[mf][nf], alf[mf], b0, b1);
                }
            }
        }
        __syncthreads();
    }
}

__device__ __forceinline__ void gemm_init(GemmCtx& g, int t) {
    const int lane = t & 31, warp = t >> 5;
    g.mbase = (warp >> 2) * 64;
    g.nbase = (warp & 3) * 32;
    g.lr16  = lane & 15;
    g.lhalf = lane >> 4;
    g.lrow0 = t >> 3;
    g.lck   = t & 7;
}

// ---- merged QKV GEMM: z=0 Q(rope->bf16), z=1 K(fp32 out + rope->bf16), z=2 V(fp32) ----
__global__ void __launch_bounds__(256, 1)
gemm_qkv(const __nv_bfloat16* __restrict__ Ah, const __nv_bfloat16* __restrict__ Al,
         const __nv_bfloat16* __restrict__ Wh, const __nv_bfloat16* __restrict__ Wl,
         __nv_bfloat16* __restrict__ qh, __nv_bfloat16* __restrict__ ql,
         __nv_bfloat16* __restrict__ kh, __nv_bfloat16* __restrict__ kl,
         float* __restrict__ outK, float* __restrict__ outV)
{
    extern __shared__ char smem[];
    const uint32_t sb = smem_u32(smem);
    const int t = threadIdx.x;
    const int bn = blockIdx.x, bm = blockIdx.y, z = blockIdx.z;

    GemmCtx g;
    gemm_init(g, t);
    const size_t woff = (size_t)EMB * EMB;
    gemm_mainloop(g, sb,
                  (const char*)(Ah + (size_t)bm * 128 * EMB),
                  (const char*)(Al + (size_t)bm * 128 * EMB),
                  (const char*)(Wh + z * woff + (size_t)bn * 128 * EMB),
                  (const char*)(Wl + z * woff + (size_t)bn * 128 * EMB));

    const int lane = t & 31;
    const int gid = lane >> 2, qd = lane & 3;

    if (z == 2) {
        // V: fp32 head-layout store
        #pragma unroll
        for (int mf = 0; mf < 4; mf++)
            #pragma unroll
            for (int half = 0; half < 2; half++) {
                int row = bm * 128 + g.mbase + mf * 16 + half * 8 + gid;
                int b = row >> 11, s = row & (S_LEN - 1);
                float* dst = outV + (((size_t)(b * NH + bn) * S_LEN + s) << 7);
                #pragma unroll
                for (int nf = 0; nf < 4; nf++) {
                    int col = g.nbase + nf * 8 + qd * 2;
                    *(float2*)(dst + col) = make_float2(g.acc[mf][nf][half*2],
                                                        g.acc[mf][nf][half*2+1]);
                }
            }
        return;
    }

    // Q/K: RoPE + bf16 hi/lo split epilogue (pair = (d, d+1), d even)
    float fr[4];
    #pragma unroll
    for (int nf = 0; nf < 4; nf++) {
        int d = g.nbase + nf * 8 + qd * 2;
        fr[nf] = powf(10000.0f, -(float)d / 128.0f);
    }
    __nv_bfloat16* oh = (z == 0) ? qh : kh;
    __nv_bfloat16* ol = (z == 0) ? ql : kl;
    #pragma unroll
    for (int mf = 0; mf < 4; mf++)
        #pragma unroll
        for (int half = 0; half < 2; half++) {
            int row = bm * 128 + g.mbase + mf * 16 + half * 8 + gid;
            int b = row >> 11, s = row & (S_LEN - 1);
            size_t base = ((size_t)(b * NH + bn) * S_LEN + s) << 7;
            #pragma unroll
            for (int nf = 0; nf < 4; nf++) {
                int d = g.nbase + nf * 8 + qd * 2;
                float x1 = g.acc[mf][nf][half*2], x2 = g.acc[mf][nf][half*2+1];
                if (z == 1)
                    *(float2*)(outK + base + d) = make_float2(x1, x2);
                float sn, cs;
                sincosf((float)s * fr[nf], &sn, &cs);
                split_store(oh, ol, base + d, x1 * cs - x2 * sn, x1 * sn + x2 * cs);
            }
        }
}

// ---- Wo GEMM: row-major fp32 out ----
__global__ void __launch_bounds__(256, 1)
gemm_wo(const __nv_bfloat16* __restrict__ Ah, const __nv_bfloat16* __restrict__ Al,
        const __nv_bfloat16* __restrict__ Bh, const __nv_bfloat16* __restrict__ Bl,
        float* __restrict__ C)
{
    extern __shared__ char smem[];
    const uint32_t sb = smem_u32(smem);
    const int t = threadIdx.x;
    const int bn = blockIdx.x, bm = blockIdx.y;

    GemmCtx g;
    gemm_init(g, t);
    gemm_mainloop(g, sb,
                  (const char*)(Ah + (size_t)bm * 128 * EMB),
                  (const char*)(Al + (size_t)bm * 128 * EMB),
                  (const char*)(Bh + (size_t)bn * 128 * EMB),
                  (const char*)(Bl + (size_t)bn * 128 * EMB));

    const int lane = t & 31;
    const int gid = lane >> 2, qd = lane & 3;
    #pragma unroll
    for (int mf = 0; mf < 4; mf++)
        #pragma unroll
        for (int half = 0; half < 2; half++) {
            int row = bm * 128 + g.mbase + mf * 16 + half * 8 + gid;
            float* dst = C + (size_t)row * EMB + bn * 128;
            #pragma unroll
            for (int nf = 0; nf < 4; nf++) {
                int col = g.nbase + nf * 8 + qd * 2;
                *(float2*)(dst + col) = make_float2(g.acc[mf][nf][half*2],
                                                    g.acc[mf][nf][half*2+1]);
            }
        }
}

// ============================================================================
// V transpose + split: (B,H,S,D) fp32 -> (B,H,D,S) bf16 hi/lo
// ============================================================================
__global__ void vsplit_t(const float* __restrict__ v,
                         __nv_bfloat16* __restrict__ vth, __nv_bfloat16* __restrict__ vtl)
{
    __shared__ float tile[32][33];
    int tx = threadIdx.x, ty = threadIdx.y;     // block (32, 8)
    int s0 = blockIdx.x * 32, d0 = blockIdx.y * 32, bh = blockIdx.z;

    #pragma unroll
    for (int k = 0; k < 4; k++) {
        int s = s0 + ty + k * 8;
        tile[ty + k * 8][tx] = v[((size_t)bh * S_LEN + s) * HD + d0 + tx];
    }
    __syncthreads();
    #pragma unroll
    for (int k = 0; k < 4; k++) {
        int d = d0 + ty + k * 8;
        float x = tile[tx][ty + k * 8];
        __nv_bfloat16 h = __float2bfloat16(x);
        size_t o = ((size_t)bh * HD + d) * S_LEN + s0 + tx;
        vth[o] = h;
        vtl[o] = __float2bfloat16(x - __bfloat162float(h));
    }
}

// ============================================================================
// HMMA flash attention (causal), software-pipelined: PV(j-1) issued right
// after S(j); P carried in registers. 2 K stages + 3 V stages.
// smem: Q 64K | K stages 64K..64K+2*32K | V stages 128K..128K+3*32K = 224K.
// Output fused: ctx bf16 hi/lo split written directly to ah/al.
// ============================================================================
#define SK_OFF 65536
#define SV_OFF 131072
#define ATT_SMEM (65536 + 2*32768 + 3*32768)   // 229376

__global__ void __launch_bounds__(256, 1)
attn_mma(const __nv_bfloat16* __restrict__ qh, const __nv_bfloat16* __restrict__ ql,
         const __nv_bfloat16* __restrict__ kh, const __nv_bfloat16* __restrict__ kl,
         const __nv_bfloat16* __restrict__ vth, const __nv_bfloat16* __restrict__ vtl,
         __nv_bfloat16* __restrict__ ch, __nv_bfloat16* __restrict__ cl)
{
    extern __shared__ char smem[];
    const uint32_t sb = smem_u32(smem);
    const int t    = threadIdx.x;
    const int lane = t & 31;
    const int w    = t >> 5;
    const int qt   = (int)gridDim.x - 1 - (int)blockIdx.x;   // heavy tiles first
    const int bh   = blockIdx.y;

    const int lr16  = lane & 15;
    const int lhalf = lane >> 4;
    const int gid   = lane >> 2;
    const int qd    = lane & 3;

    // ---- load Q tile (128 x 128 bf16, hi+lo), once ----
    #pragma unroll
    for (int it = 0; it < 8; it++) {
        int idx = t + it * 256;
        int row = idx >> 4, c = idx & 15;
        uint32_t sw = (uint32_t)(row * 256 + ((c ^ (row & 7)) << 4));
        size_t gq = (((size_t)bh * S_LEN) + qt * 128 + row) * HD + c * 8;
        cp16(sb +         sw, qh + gq);
        cp16(sb + 32768 + sw, ql + gq);
    }

    auto load_kv = [&](int j, int kb, int vb) {
        const uint32_t stK = sb + SK_OFF + kb * 32768;
        const uint32_t stV = sb + SV_OFF + vb * 32768;
        #pragma unroll
        for (int it = 0; it < 4; it++) {
            int idx = t + it * 256;
            int rowK = idx >> 4, cK = idx & 15;
            uint32_t swK = (uint32_t)(rowK * 256 + ((cK ^ (rowK & 7)) << 4));
            size_t gk = (((size_t)bh * S_LEN) + j * 64 + rowK) * HD + cK * 8;
            cp16(stK +         swK, kh + gk);
            cp16(stK + 16384 + swK, kl + gk);
            int rowV = idx >> 3, cV = idx & 7;
            uint32_t swV = (uint32_t)(rowV * 128 + ((cV ^ (rowV & 7)) << 4));
            size_t gv = (((size_t)bh * HD) + rowV) * S_LEN + j * 64 + cV * 8;
            cp16(stV +         swV, vth + gv);
            cp16(stV + 16384 + swV, vtl + gv);
        }
    };

    load_kv(0, 0, 0);
    CP_COMMIT();

    float oacc[16][4];
    #pragma unroll
    for (int i = 0; i < 16; i++)
        #pragma unroll
        for (int c = 0; c < 4; c++) oacc[i][c] = 0.f;
    float mp0 = -1e30f, mp1 = -1e30f, ls0 = 0.f, ls1 = 0.f;
    uint32_t ppa[4][4], ppb[4][4];   // carried P (hi/lo packed bf16x2)

    const float scale = 0.088388347648318447f;  // 1/sqrt(128)
    const int jmax = 2 * qt + 1;
    const int row0g = qt * 128 + w * 16 + gid;
    const int row1g = row0g + 8;

    auto do_pv = [&](int vb) {
        const uint32_t stVh = sb + SV_OFF + vb * 32768;
        const uint32_t stVl = stVh + 16384;
        #pragma unroll
        for (int ks = 0; ks < 4; ks++) {
            const int c16 = ks * 2 + lhalf;
            #pragma unroll
            for (int nb = 0; nb < 8; nb++) {
                int rowB = nb * 16 + lr16;
                uint32_t offB = (uint32_t)(rowB * 128 + ((c16 ^ (rowB & 7)) << 4));
                uint32_t vh4[4], vl4[4];
                ldsm4(vh4, stVh + offB);
                ldsm4(vl4, stVl + offB);
                mma16816(oacc[2*nb],   ppa[ks], vh4[0], vh4[2]);
                mma16816(oacc[2*nb],   ppa[ks], vl4[0], vl4[2]);
                mma16816(oacc[2*nb],   ppb[ks], vh4[0], vh4[2]);
                mma16816(oacc[2*nb+1], ppa[ks], vh4[1], vh4[3]);
                mma16816(oacc[2*nb+1], ppa[ks], vl4[1], vl4[3]);
                mma16816(oacc[2*nb+1], ppb[ks], vh4[1], vh4[3]);
            }
        }
    };

    for (int j = 0; j <= jmax; j++) {
        if (j + 1 <= jmax) load_kv(j + 1, (j + 1) & 1, (j + 1) % 3);
        CP_COMMIT();
        CP_WAIT1();
        __syncthreads();

        const uint32_t stKh = sb + SK_OFF + (j & 1) * 32768;
        const uint32_t stKl = stKh + 16384;

        // ---- S = Q K^T ----
        float sacc[8][4];
        #pragma unroll
        for (int i = 0; i < 8; i++)
            #pragma unroll
            for (int c = 0; c < 4; c++) sacc[i][c] = 0.f;

        #pragma unroll
        for (int kd = 0; kd < 8; kd++) {
            const int c16 = kd * 2 + lhalf;
            int rowA = w * 16 + lr16;
            uint32_t offA = (uint32_t)(rowA * 256 + ((c16 ^ (rowA & 7)) << 4));
            uint32_t ah4[4], al4[4];
            ldsm4(ah4, sb +         offA);
            ldsm4(al4, sb + 32768 + offA);
            #pragma unroll
            for (int nb = 0; nb < 4; nb++) {
                int rowB = nb * 16 + lr16;
                uint32_t offB = (uint32_t)(rowB * 256 + ((c16 ^ (rowB & 7)) << 4));
                uint32_t bh4[4], bl4[4];
                ldsm4(bh4, stKh + offB);
                ldsm4(bl4, stKl + offB);
                mma16816(sacc[2*nb],   ah4, bh4[0], bh4[2]);
                mma16816(sacc[2*nb],   ah4, bl4[0], bl4[2]);
                mma16816(sacc[2*nb],   al4, bh4[0], bh4[2]);
                mma16816(sacc[2*nb+1], ah4, bh4[1], bh4[3]);
                mma16816(sacc[2*nb+1], ah4, bl4[1], bl4[3]);
                mma16816(sacc[2*nb+1], al4, bh4[1], bh4[3]);
            }
        }

        // ---- PV for previous tile (P in registers), overlaps softmax below ----
        if (j > 0) do_pv((j - 1) % 3);

        // ---- online softmax -> pack P into carried registers ----
        const bool need_mask = (j * 64 + 63) > (qt * 128 + w * 16);
        float mx0 = -1e30f, mx1 = -1e30f;
        #pragma unroll
        for (int nf = 0; nf < 8; nf++) {
            int colg = j * 64 + nf * 8 + qd * 2;
            float v0 = sacc[nf][0] * scale;
            float v1 = sacc[nf][1] * scale;
            float v2 = sacc[nf][2] * scale;
            float v3 = sacc[nf][3] * scale;
            if (need_mask) {
                if (colg     > row0g) v0 = -1e30f;
                if (colg + 1 > row0g) v1 = -1e30f;
                if (colg     > row1g) v2 = -1e30f;
                if (colg + 1 > row1g) v3 = -1e30f;
            }
            sacc[nf][0] = v0; sacc[nf][1] = v1; sacc[nf][2] = v2; sacc[nf][3] = v3;
            mx0 = fmaxf(mx0, fmaxf(v0, v1));
            mx1 = fmaxf(mx1, fmaxf(v2, v3));
        }
        mx0 = fmaxf(mx0, __shfl_xor_sync(0xffffffffu, mx0, 1));
        mx0 = fmaxf(mx0, __shfl_xor_sync(0xffffffffu, mx0, 2));
        mx1 = fmaxf(mx1, __shfl_xor_sync(0xffffffffu, mx1, 1));
        mx1 = fmaxf(mx1, __shfl_xor_sync(0xffffffffu, mx1, 2));
        float mn0 = fmaxf(mp0, mx0), mn1 = fmaxf(mp1, mx1);
        float a0 = __expf(mp0 - mn0), a1 = __expf(mp1 - mn1);
        mp0 = mn0; mp1 = mn1;
        float pl0 = 0.f, pl1 = 0.f;
        #pragma unroll
        for (int nf = 0; nf < 8; nf++) {
            float p0 = __expf(sacc[nf][0] - mn0);
            float p1 = __expf(sacc[nf][1] - mn0);
            float p2 = __expf(sacc[nf][2] - mn1);
            float p3 = __expf(sacc[nf][3] - mn1);
            sacc[nf][0] = p0; sacc[nf][1] = p1; sacc[nf][2] = p2; sacc[nf][3] = p3;
            pl0 += p0 + p1; pl1 += p2 + p3;
        }
        ls0 = ls0 * a0 + pl0;
        ls1 = ls1 * a1 + pl1;
        #pragma unroll
        for (int nf = 0; nf < 16; nf++) {
            oacc[nf][0] *= a0; oacc[nf][1] *= a0;
            oacc[nf][2] *= a1; oacc[nf][3] *= a1;
        }
        // pack P -> ppa/ppb (hi + residual)
        #pragma unroll
        for (int ks = 0; ks < 4; ks++) {
            float p00 = sacc[2*ks][0],   p01 = sacc[2*ks][1];
            float p02 = sacc[2*ks][2],   p03 = sacc[2*ks][3];
            float p10 = sacc[2*ks+1][0], p11 = sacc[2*ks+1][1];
            float p12 = sacc[2*ks+1][2], p13 = sacc[2*ks+1][3];
            ppa[ks][0] = pack_bf16x2(p00, p01);
            ppa[ks][1] = pack_bf16x2(p02, p03);
            ppa[ks][2] = pack_bf16x2(p10, p11);
            ppa[ks][3] = pack_bf16x2(p12, p13);
            __nv_bfloat162 h;
            h = *(__nv_bfloat162*)&ppa[ks][0];
            ppb[ks][0] = pack_bf16x2(p00 - __bfloat162float(h.x), p01 - __bfloat162float(h.y));
            h = *(__nv_bfloat162*)&ppa[ks][1];
            ppb[ks][1] = pack_bf16x2(p02 - __bfloat162float(h.x), p03 - __bfloat162float(h.y));
            h = *(__nv_bfloat162*)&ppa[ks][2];
            ppb[ks][2] = pack_bf16x2(p10 - __bfloat162float(h.x), p11 - __bfloat162float(h.y));
            h = *(__nv_bfloat162*)&ppa[ks][3];
            ppb[ks][3] = pack_bf16x2(p12 - __bfloat162float(h.x), p13 - __bfloat162float(h.y));
        }
        __syncthreads();
    }

    // ---- final PV for tile jmax ----
    do_pv(jmax % 3);

    // ---- finalize + fused bf16 hi/lo ctx write (B,S,E) ----
    ls0 += __shfl_xor_sync(0xffffffffu, ls0, 1);
    ls0 += __shfl_xor_sync(0xffffffffu, ls0, 2);
    ls1 += __shfl_xor_sync(0xffffffffu, ls1, 1);
    ls1 += __shfl_xor_sync(0xffffffffu, ls1, 2);
    float rn0 = 1.f / ls0, rn1 = 1.f / ls1;

    int b = bh >> 4, h = bh & 15;
    size_t e0 = ((size_t)b * S_LEN + row0g) * EMB + h * HD;
    size_t e1 = e0 + (size_t)8 * EMB;
    #pragma unroll
    for (int nf = 0; nf < 16; nf++) {
        int col = nf * 8 + qd * 2;
        split_store(ch, cl, e0 + col, oacc[nf][0] * rn0, oacc[nf][1] * rn0);
        split_store(ch, cl, e1 + col, oacc[nf][2] * rn1, oacc[nf][3] * rn1);
    }
}

// ============================================================================
// launch
// ============================================================================
extern "C" void kernel_launch(void* const* d_in, const int* in_sizes, int n_in,
                              void* d_out, int out_size)
{
    (void)in_sizes; (void)n_in; (void)out_size;
    const float* x  = (const float*)d_in[0];
    const float* Wq = (const float*)d_in[1];
    const float* Wk = (const float*)d_in[2];
    const float* Wv = (const float*)d_in[3];
    const float* Wo = (const float*)d_in[4];

    float* out  = (float*)d_out;
    float* outK = out  + (size_t)NB * S_LEN * EMB;
    float* outV = outK + (size_t)BHN * S_LEN * HD;

    __nv_bfloat16 *ah, *al, *wh, *wl, *qhp, *qlp, *khp, *klp, *vthp, *vtlp;
    cudaGetSymbolAddress((void**)&ah,   g_ah);
    cudaGetSymbolAddress((void**)&al,   g_al);
    cudaGetSymbolAddress((void**)&wh,   g_wh);
    cudaGetSymbolAddress((void**)&wl,   g_wl);
    cudaGetSymbolAddress((void**)&qhp,  g_qh);
    cudaGetSymbolAddress((void**)&qlp,  g_ql);
    cudaGetSymbolAddress((void**)&khp,  g_kh);
    cudaGetSymbolAddress((void**)&klp,  g_kl);
    cudaGetSymbolAddress((void**)&vthp, g_vth);
    cudaGetSymbolAddress((void**)&vtlp, g_vtl);

    cudaFuncSetAttribute(attn_mma,
                         cudaFuncAttributeMaxDynamicSharedMemorySize, ATT_SMEM);
    cudaFuncSetAttribute(gemm_qkv,
                         cudaFuncAttributeMaxDynamicSharedMemorySize, GEMM_SMEM);
    cudaFuncSetAttribute(gemm_wo,
                         cudaFuncAttributeMaxDynamicSharedMemorySize, GEMM_SMEM);

    const size_t woff = (size_t)EMB * EMB;

    int n4x = M_TOT * EMB / 4;
    split_bf16<<<(n4x + 255) / 256, 256>>>((const float4*)x, ah, al, n4x);
    int n4w = EMB * EMB / 4;
    split_bf16<<<(n4w + 255) / 256, 256>>>((const float4*)Wq, wh + 0*woff, wl + 0*woff, n4w);
    split_bf16<<<(n4w + 255) / 256, 256>>>((const float4*)Wk, wh + 1*woff, wl + 1*woff, n4w);
    split_bf16<<<(n4w + 255) / 256, 256>>>((const float4*)Wv, wh + 2*woff, wl + 2*woff, n4w);
    split_bf16<<<(n4w + 255) / 256, 256>>>((const float4*)Wo, wh + 3*woff, wl + 3*woff, n4w);

    // fused QKV projection (+RoPE/split for Q,K), one launch
    gemm_qkv<<<dim3(EMB / 128, M_TOT / 128, 3), 256, GEMM_SMEM>>>(
        ah, al, wh, wl, qhp, qlp, khp, klp, outK, outV);

    vsplit_t<<<dim3(S_LEN / 32, HD / 32, BHN), dim3(32, 8)>>>(outV, vthp, vtlp);

    // attention writes ctx directly as bf16 hi/lo into ah/al
    attn_mma<<<dim3(S_LEN / 128, BHN), 256, ATT_SMEM>>>(qhp, qlp, khp, klp,
                                                        vthp, vtlp, ah, al);

    gemm_wo<<<dim3(EMB / 128, M_TOT / 128), 256, GEMM_SMEM>>>(
        ah, al, wh + 3*woff, wl + 3*woff, out);
}